// round 4
// baseline (speedup 1.0000x reference)
#include <cuda_runtime.h>
#include <cuda_bf16.h>
#include <cstdint>
#include <cstddef>

// ---------------------------------------------------------------------------
// WinBasedAttention (SwinV2 window attention, shift=0) for B200/sm_100a
//   B=4, C=192, H=W=256, window 8x8 (N=64), heads=8, head_dim=24
// Launches:
//   k_table  : CPB MLP  -> g_table[225][8]
//   k_bias   : gather + 16*sigmoid -> g_bias16[8][64][64]; g_scale[8]
//   k_gemm<0>: QKV = Wqkv @ X   (TF32 mma)  -> g_qkv  [4][576][65536]
//   k_attn   : per-window cosine attention  -> g_att  [4][192][65536]
//   k_gemm<1>: out = Wproj @ g_att + b + x  -> d_out
// ---------------------------------------------------------------------------

namespace {
constexpr int CH    = 192;
constexpr int NHD   = 8;
constexpr int PIX   = 65536;
constexpr int BATCH = 4;
constexpr int OC3   = 576;
constexpr int TSTR  = 68;                 // smem row stride in k_attn
constexpr int ATTN_SMEM_FLOATS = 576 * TSTR + 1024;
}

__device__ float g_qkv[(size_t)BATCH * OC3 * PIX];
__device__ float g_att[(size_t)BATCH * CH  * PIX];
__device__ float g_table[225 * NHD];
__device__ float g_bias16[NHD * 64 * 64];
__device__ float g_scale[NHD];

// ---------------------------------------------------------------------------
__device__ __forceinline__ uint32_t f2tf(float x) {
    uint32_t u;
    asm volatile("cvt.rna.tf32.f32 %0, %1;" : "=r"(u) : "f"(x));
    return u;
}

__device__ __forceinline__ void mma8(float* d, const uint32_t* a, const uint32_t* b) {
    asm volatile(
        "mma.sync.aligned.m16n8k8.row.col.f32.tf32.tf32.f32 "
        "{%0,%1,%2,%3},{%4,%5,%6,%7},{%8,%9},{%0,%1,%2,%3};"
        : "+f"(d[0]), "+f"(d[1]), "+f"(d[2]), "+f"(d[3])
        : "r"(a[0]), "r"(a[1]), "r"(a[2]), "r"(a[3]), "r"(b[0]), "r"(b[1]));
}

__device__ __forceinline__ void cp16(float* s, const float* g) {
    uint32_t sa = (uint32_t)__cvta_generic_to_shared(s);
    asm volatile("cp.async.ca.shared.global [%0], [%1], 16;" :: "r"(sa), "l"(g));
}

// ---------------------------------------------------------------------------
// CPB MLP: table[i][h] = (relu(rct[i] @ w1 + b1) @ w2)[h]   grid 225, block 128
// ---------------------------------------------------------------------------
__device__ __forceinline__ float relcoord(int c) {
    float t = (float)c * (8.0f / 7.0f);
    float v = log2f(fabsf(t) + 1.0f) * (1.0f / 3.0f);   // /log2(8)
    return (t < 0.f) ? -v : (t > 0.f ? v : 0.f);
}

__global__ void k_table(const float* __restrict__ w1, const float* __restrict__ b1,
                        const float* __restrict__ w2) {
    const int i = blockIdx.x;
    const float r0 = relcoord(i / 15 - 7);
    const float r1 = relcoord(i % 15 - 7);
    float acc[8] = {0.f, 0.f, 0.f, 0.f, 0.f, 0.f, 0.f, 0.f};
    for (int j = threadIdx.x; j < 512; j += 128) {
        float h = fmaf(r0, w1[j], fmaf(r1, w1[512 + j], b1[j]));
        h = fmaxf(h, 0.f);
        #pragma unroll
        for (int q = 0; q < 8; q++) acc[q] = fmaf(h, w2[j * 8 + q], acc[q]);
    }
    __shared__ float red[4][8];
    #pragma unroll
    for (int q = 0; q < 8; q++) {
        float v = acc[q];
        v += __shfl_xor_sync(0xffffffffu, v, 16);
        v += __shfl_xor_sync(0xffffffffu, v, 8);
        v += __shfl_xor_sync(0xffffffffu, v, 4);
        v += __shfl_xor_sync(0xffffffffu, v, 2);
        v += __shfl_xor_sync(0xffffffffu, v, 1);
        if ((threadIdx.x & 31) == 0) red[threadIdx.x >> 5][q] = v;
    }
    __syncthreads();
    if (threadIdx.x < 8) {
        g_table[i * 8 + threadIdx.x] =
            red[0][threadIdx.x] + red[1][threadIdx.x] +
            red[2][threadIdx.x] + red[3][threadIdx.x];
    }
}

// ---------------------------------------------------------------------------
// bias16[h][n][m] = 16*sigmoid(table[rpi(n,m)][h]);  g_scale[h]
// grid 64, block 512
// ---------------------------------------------------------------------------
__global__ void k_bias(const float* __restrict__ ls) {
    const int n = blockIdx.x;
    const int t = threadIdx.x;
    const int h = t >> 6, m = t & 63;
    const int r1 = n >> 3, c1 = n & 7, r2 = m >> 3, c2 = m & 7;
    const int idx = (r1 - r2 + 7) * 15 + (c1 - c2 + 7);
    const float v = g_table[idx * 8 + h];
    g_bias16[(h << 12) + (n << 6) + m] = 16.f / (1.f + __expf(-v));
    if (n == 0 && t < 8)
        g_scale[t] = expf(fminf(ls[t], 4.6051701859880914f));   // ln(100)
}

// ---------------------------------------------------------------------------
// C[M x 65536] = W[M x 192] @ B[192 x 65536]  (TF32 mma)
// MODE 0: QKV, bias=[q_bias,0,v_bias], out g_qkv.  MODE 1: proj + b + residual.
// CTA 64x128, BK=16, 8 warps (2x4), warp tile 32x32, double-buffered cp.async.
// ---------------------------------------------------------------------------
template <int MODE>
__global__ void __launch_bounds__(256) k_gemm(const float* __restrict__ Bg,
                                              const float* __restrict__ W,
                                              const float* __restrict__ bias0,
                                              const float* __restrict__ bias1,
                                              const float* __restrict__ resid,
                                              float* __restrict__ outp) {
    __shared__ float smem[8704];          // 34816 B; reused as sO in epilogue
    float* sA = smem;                     // [2][64][20]
    float* sB = smem + 2560;              // [2][16][136]
    float* sO = smem;                     // [64][136]

    const int tid = threadIdx.x;
    const int bn = blockIdx.x * 128;
    const int bm = blockIdx.y * 64;
    const int b  = blockIdx.z;
    const float* src = (MODE == 0 ? Bg : g_att) + (size_t)b * CH * PIX;
    float* dst = (MODE == 0 ? g_qkv + (size_t)b * OC3 * PIX
                            : outp + (size_t)b * CH * PIX);

    const int warp = tid >> 5, lane = tid & 31, g = lane >> 2, tg = lane & 3;
    const int wm = warp >> 2, wn = warp & 3;

    float acc[2][4][4];
    #pragma unroll
    for (int i = 0; i < 2; i++)
        #pragma unroll
        for (int j = 0; j < 4; j++)
            #pragma unroll
            for (int k = 0; k < 4; k++) acc[i][j][k] = 0.f;

    auto stage = [&](int buf, int k0) {
        {
            int row = tid >> 2, cc = tid & 3;
            cp16(&sA[buf * 1280 + row * 20 + cc * 4],
                 &W[(bm + row) * CH + k0 + cc * 4]);
        }
        #pragma unroll
        for (int j = 0; j < 2; j++) {
            int chunk = tid + j * 256;
            int row = chunk >> 5, cc = chunk & 31;
            cp16(&sB[buf * 2176 + row * 136 + cc * 4],
                 &src[(size_t)(k0 + row) * PIX + bn + cc * 4]);
        }
        asm volatile("cp.async.commit_group;");
    };

    stage(0, 0);
    #pragma unroll 1
    for (int kk = 0; kk < 12; kk++) {
        const int buf = kk & 1;
        if (kk < 11) {
            stage(buf ^ 1, (kk + 1) * 16);
            asm volatile("cp.async.wait_group 1;");
        } else {
            asm volatile("cp.async.wait_group 0;");
        }
        __syncthreads();
        const float* A0 = sA + buf * 1280;
        const float* B0 = sB + buf * 2176;
        #pragma unroll
        for (int ks = 0; ks < 2; ks++) {
            const int k = ks * 8;
            uint32_t bf[4][2];
            #pragma unroll
            for (int nt = 0; nt < 4; nt++) {
                bf[nt][0] = f2tf(B0[(k + tg) * 136 + wn * 32 + nt * 8 + g]);
                bf[nt][1] = f2tf(B0[(k + tg + 4) * 136 + wn * 32 + nt * 8 + g]);
            }
            #pragma unroll
            for (int mt = 0; mt < 2; mt++) {
                const int r0 = wm * 32 + mt * 16;
                uint32_t af[4];
                af[0] = f2tf(A0[(r0 + g) * 20 + k + tg]);
                af[1] = f2tf(A0[(r0 + g + 8) * 20 + k + tg]);
                af[2] = f2tf(A0[(r0 + g) * 20 + k + tg + 4]);
                af[3] = f2tf(A0[(r0 + g + 8) * 20 + k + tg + 4]);
                #pragma unroll
                for (int nt = 0; nt < 4; nt++) mma8(acc[mt][nt], af, bf[nt]);
            }
        }
        __syncthreads();
    }

    #pragma unroll
    for (int mt = 0; mt < 2; mt++) {
        const int r0 = wm * 32 + mt * 16;
        const int o_lo = bm + r0 + g, o_hi = o_lo + 8;
        float blo, bhi;
        if (MODE == 0) {
            blo = (o_lo < 192) ? bias0[o_lo] : (o_lo < 384 ? 0.f : bias1[o_lo - 384]);
            bhi = (o_hi < 192) ? bias0[o_hi] : (o_hi < 384 ? 0.f : bias1[o_hi - 384]);
        } else {
            blo = bias0[o_lo];
            bhi = bias0[o_hi];
        }
        #pragma unroll
        for (int nt = 0; nt < 4; nt++) {
            const int c0 = wn * 32 + nt * 8 + 2 * tg;
            sO[(r0 + g) * 136 + c0]         = acc[mt][nt][0] + blo;
            sO[(r0 + g) * 136 + c0 + 1]     = acc[mt][nt][1] + blo;
            sO[(r0 + g + 8) * 136 + c0]     = acc[mt][nt][2] + bhi;
            sO[(r0 + g + 8) * 136 + c0 + 1] = acc[mt][nt][3] + bhi;
        }
    }
    __syncthreads();
    #pragma unroll
    for (int j = 0; j < 8; j++) {
        const int idx = tid + j * 256;          // 2048 float4s
        const int row = idx >> 5, c4 = (idx & 31) * 4;
        float4 v;
        v.x = sO[row * 136 + c4];
        v.y = sO[row * 136 + c4 + 1];
        v.z = sO[row * 136 + c4 + 2];
        v.w = sO[row * 136 + c4 + 3];
        const size_t go = (size_t)(bm + row) * PIX + bn + c4;
        if (MODE == 1) {
            const float4 r4 = *(const float4*)&resid[(size_t)b * CH * PIX + go];
            v.x += r4.x; v.y += r4.y; v.z += r4.z; v.w += r4.w;
        }
        *(float4*)&dst[go] = v;
    }
}

// ---------------------------------------------------------------------------
// Per-window attention. grid 4096 = (b, wy, wx); 256 threads = 8 warps = 8 heads.
// smem tile [576][68] (stride 68 -> conflict-free for both QK and V patterns).
// ---------------------------------------------------------------------------
__global__ void __launch_bounds__(256, 1) k_attn() {
    extern __shared__ float sT[];                  // [576][TSTR]
    float* sInvQ = sT + 576 * TSTR;                // [8][64]
    float* sInvK = sInvQ + 512;                    // [8][64]

    const int tid = threadIdx.x, lane = tid & 31, warp = tid >> 5;
    const int g = lane >> 2, tg = lane & 3;
    const int bx = blockIdx.x;
    const int wx = bx & 31, hy = (bx >> 5) & 31, b = bx >> 10;
    const int p0 = (hy << 11) + (wx << 3);
    const float* src = g_qkv + (size_t)b * OC3 * PIX + p0;

    // load QKV tile (window gather; 8 consecutive floats = one 32B sector)
    for (int idx = tid; idx < 576 * 64; idx += 256) {
        const int o = idx >> 6, t = idx & 63;
        sT[o * TSTR + t] = src[(size_t)o * PIX + ((t & 56) << 5) + (t & 7)];
    }
    __syncthreads();

    // per-(head,token) inverse norms; fold logit scale into q side
    for (int pr = tid; pr < 512; pr += 256) {
        const int h = pr >> 6, t = pr & 63;
        const float* qp = sT + (h * 24) * TSTR + t;
        const float* kp = sT + (192 + h * 24) * TSTR + t;
        float sq = 0.f, sk = 0.f;
        #pragma unroll
        for (int d = 0; d < 24; d++) {
            float q = qp[d * TSTR], k = kp[d * TSTR];
            sq = fmaf(q, q, sq);
            sk = fmaf(k, k, sk);
        }
        sInvQ[pr] = g_scale[h] / fmaxf(sqrtf(sq), 1e-12f);
        sInvK[pr] = 1.0f / fmaxf(sqrtf(sk), 1e-12f);
    }
    __syncthreads();

    // scale q,k in place
    for (int idx = tid; idx < 384 * 64; idx += 256) {
        const int o = idx >> 6, t = idx & 63;
        const float m = (o < 192) ? sInvQ[(o / 24) * 64 + t]
                                  : sInvK[((o - 192) / 24) * 64 + t];
        sT[o * TSTR + t] *= m;
    }
    __syncthreads();

    const int h = warp;
    const float* Q = sT + (h * 24) * TSTR;
    const float* K = sT + (192 + h * 24) * TSTR;
    const float* V = sT + (384 + h * 24) * TSTR;
    const float* bias = g_bias16 + (h << 12);
    float* dst = g_att + (size_t)b * CH * PIX + (size_t)(h * 24) * PIX + p0;

    const int srcLo = (lane & 28) | (tg >> 1);
    const int srcHi = srcLo + 2;
    const bool odd = (tg & 1);

    #pragma unroll 1
    for (int mt = 0; mt < 4; mt++) {
        const int m0 = mt * 16;
        // ---- S = (scaled q)^T k   [16 rows x 64 cols] ----
        float s[8][4];
        #pragma unroll
        for (int nt = 0; nt < 8; nt++)
            #pragma unroll
            for (int e = 0; e < 4; e++) s[nt][e] = 0.f;

        #pragma unroll
        for (int kt = 0; kt < 3; kt++) {
            const int k0 = kt * 8;
            uint32_t a[4];
            a[0] = f2tf(Q[(k0 + tg) * TSTR + m0 + g]);
            a[1] = f2tf(Q[(k0 + tg) * TSTR + m0 + g + 8]);
            a[2] = f2tf(Q[(k0 + tg + 4) * TSTR + m0 + g]);
            a[3] = f2tf(Q[(k0 + tg + 4) * TSTR + m0 + g + 8]);
            #pragma unroll
            for (int nt = 0; nt < 8; nt++) {
                uint32_t bb[2];
                bb[0] = f2tf(K[(k0 + tg) * TSTR + nt * 8 + g]);
                bb[1] = f2tf(K[(k0 + tg + 4) * TSTR + nt * 8 + g]);
                mma8(s[nt], a, bb);
            }
        }

        // ---- + bias, softmax (rows r1 = m0+g, r2 = r1+8) ----
        const int r1 = m0 + g, r2 = r1 + 8;
        float mx1 = -1e30f, mx2 = -1e30f;
        #pragma unroll
        for (int nt = 0; nt < 8; nt++) {
            const int c0 = nt * 8 + 2 * tg;
            const float2 b1v = *(const float2*)&bias[(r1 << 6) + c0];
            const float2 b2v = *(const float2*)&bias[(r2 << 6) + c0];
            s[nt][0] += b1v.x; s[nt][1] += b1v.y;
            s[nt][2] += b2v.x; s[nt][3] += b2v.y;
            mx1 = fmaxf(mx1, fmaxf(s[nt][0], s[nt][1]));
            mx2 = fmaxf(mx2, fmaxf(s[nt][2], s[nt][3]));
        }
        mx1 = fmaxf(mx1, __shfl_xor_sync(0xffffffffu, mx1, 1));
        mx1 = fmaxf(mx1, __shfl_xor_sync(0xffffffffu, mx1, 2));
        mx2 = fmaxf(mx2, __shfl_xor_sync(0xffffffffu, mx2, 1));
        mx2 = fmaxf(mx2, __shfl_xor_sync(0xffffffffu, mx2, 2));
        float sum1 = 0.f, sum2 = 0.f;
        #pragma unroll
        for (int nt = 0; nt < 8; nt++) {
            s[nt][0] = __expf(s[nt][0] - mx1);
            s[nt][1] = __expf(s[nt][1] - mx1);
            s[nt][2] = __expf(s[nt][2] - mx2);
            s[nt][3] = __expf(s[nt][3] - mx2);
            sum1 += s[nt][0] + s[nt][1];
            sum2 += s[nt][2] + s[nt][3];
        }
        sum1 += __shfl_xor_sync(0xffffffffu, sum1, 1);
        sum1 += __shfl_xor_sync(0xffffffffu, sum1, 2);
        sum2 += __shfl_xor_sync(0xffffffffu, sum2, 1);
        sum2 += __shfl_xor_sync(0xffffffffu, sum2, 2);
        const float inv1 = 1.f / sum1, inv2 = 1.f / sum2;

        // ---- O(mt) = P @ V : convert P C-frag -> A-frag in registers ----
        float o_[3][4];
        #pragma unroll
        for (int nt = 0; nt < 3; nt++)
            #pragma unroll
            for (int e = 0; e < 4; e++) o_[nt][e] = 0.f;

        #pragma unroll
        for (int kt = 0; kt < 8; kt++) {
            const float v00 = __shfl_sync(0xffffffffu, s[kt][0], srcLo);
            const float v01 = __shfl_sync(0xffffffffu, s[kt][1], srcLo);
            const float v10 = __shfl_sync(0xffffffffu, s[kt][2], srcLo);
            const float v11 = __shfl_sync(0xffffffffu, s[kt][3], srcLo);
            const float w00 = __shfl_sync(0xffffffffu, s[kt][0], srcHi);
            const float w01 = __shfl_sync(0xffffffffu, s[kt][1], srcHi);
            const float w10 = __shfl_sync(0xffffffffu, s[kt][2], srcHi);
            const float w11 = __shfl_sync(0xffffffffu, s[kt][3], srcHi);
            uint32_t a[4];
            a[0] = f2tf(odd ? v01 : v00);   // P[m0+g  ][8kt+tg  ]
            a[1] = f2tf(odd ? v11 : v10);   // P[m0+g+8][8kt+tg  ]
            a[2] = f2tf(odd ? w01 : w00);   // P[m0+g  ][8kt+tg+4]
            a[3] = f2tf(odd ? w11 : w10);   // P[m0+g+8][8kt+tg+4]
            #pragma unroll
            for (int nt = 0; nt < 3; nt++) {
                uint32_t bb[2];
                bb[0] = f2tf(V[(nt * 8 + g) * TSTR + kt * 8 + tg]);
                bb[1] = f2tf(V[(nt * 8 + g) * TSTR + kt * 8 + tg + 4]);
                mma8(o_[nt], a, bb);
            }
        }

        // ---- store (fold 1/rowsum); window row = contiguous 32B sector ----
        const int p1 = ((r1 & 56) << 5) + (r1 & 7);
        const int p2 = ((r2 & 56) << 5) + (r2 & 7);
        #pragma unroll
        for (int nt = 0; nt < 3; nt++) {
            const int d0 = nt * 8 + 2 * tg;
            const size_t c1 = (size_t)d0 * PIX, c2 = c1 + PIX;
            dst[c1 + p1] = o_[nt][0] * inv1;
            dst[c2 + p1] = o_[nt][1] * inv1;
            dst[c1 + p2] = o_[nt][2] * inv2;
            dst[c2 + p2] = o_[nt][3] * inv2;
        }
    }
}

// ---------------------------------------------------------------------------
extern "C" void kernel_launch(void* const* d_in, const int* in_sizes, int n_in,
                              void* d_out, int out_size) {
    const float* x      = (const float*)d_in[0];
    // d_in[1] img_alpha unused (all-ones, no-op per reference)
    const float* qkv_w  = (const float*)d_in[2];
    const float* q_bias = (const float*)d_in[3];
    const float* v_bias = (const float*)d_in[4];
    const float* ls     = (const float*)d_in[5];
    const float* w1     = (const float*)d_in[6];
    const float* b1     = (const float*)d_in[7];
    const float* w2     = (const float*)d_in[8];
    const float* proj_w = (const float*)d_in[9];
    const float* proj_b = (const float*)d_in[10];
    float* out = (float*)d_out;

    const int attn_smem = ATTN_SMEM_FLOATS * 4;    // 160768 B
    cudaFuncSetAttribute(k_attn, cudaFuncAttributeMaxDynamicSharedMemorySize,
                         attn_smem);

    k_table<<<225, 128>>>(w1, b1, w2);
    k_bias<<<64, 512>>>(ls);
    dim3 g0(512, 9, BATCH);
    k_gemm<0><<<g0, 256>>>(x, qkv_w, q_bias, v_bias, nullptr, nullptr);
    k_attn<<<4096, 256, attn_smem>>>();
    dim3 g1(512, 3, BATCH);
    k_gemm<1><<<g1, 256>>>(nullptr, proj_w, proj_b, nullptr, x, out);
}

// round 6
// speedup vs baseline: 1.2221x; 1.2221x over previous
#include <cuda_runtime.h>
#include <cuda_bf16.h>
#include <cstdint>
#include <cstddef>

// ---------------------------------------------------------------------------
// WinBasedAttention (SwinV2 window attention, shift=0) for B200/sm_100a
//   B=4, C=192, H=W=256, window 8x8 (N=64), heads=8, head_dim=24
// R5 (re-bench): k_attn 512 thr (2 warps/head), float4 gather, norms folded
// into frags; k_gemm keeps full B strip resident (activations read once).
// ---------------------------------------------------------------------------

namespace {
constexpr int CH    = 192;
constexpr int NHD   = 8;
constexpr int PIX   = 65536;
constexpr int BATCH = 4;
constexpr int OC3   = 576;
constexpr int TSTR  = 68;                        // attn smem row stride
constexpr int ATTN_SMEM_FLOATS = 576 * TSTR + 1024;
constexpr int BSTR  = 132;                       // gemm B smem row stride
constexpr int GEMM_SMEM_FLOATS = 192 * BSTR + 2 * 64 * 20;   // 27904
}

__device__ float g_qkv[(size_t)BATCH * OC3 * PIX];
__device__ float g_att[(size_t)BATCH * CH  * PIX];
__device__ float g_table[225 * NHD];
__device__ float g_bias16[NHD * 64 * 64];
__device__ float g_scale[NHD];

// ---------------------------------------------------------------------------
__device__ __forceinline__ uint32_t f2tf(float x) {
    uint32_t u;
    asm volatile("cvt.rna.tf32.f32 %0, %1;" : "=r"(u) : "f"(x));
    return u;
}

__device__ __forceinline__ void mma8(float* d, const uint32_t* a, const uint32_t* b) {
    asm volatile(
        "mma.sync.aligned.m16n8k8.row.col.f32.tf32.tf32.f32 "
        "{%0,%1,%2,%3},{%4,%5,%6,%7},{%8,%9},{%0,%1,%2,%3};"
        : "+f"(d[0]), "+f"(d[1]), "+f"(d[2]), "+f"(d[3])
        : "r"(a[0]), "r"(a[1]), "r"(a[2]), "r"(a[3]), "r"(b[0]), "r"(b[1]));
}

__device__ __forceinline__ void cp16(float* s, const float* g) {
    uint32_t sa = (uint32_t)__cvta_generic_to_shared(s);
    asm volatile("cp.async.ca.shared.global [%0], [%1], 16;" :: "r"(sa), "l"(g));
}

// ---------------------------------------------------------------------------
// CPB MLP: table[i][h] = (relu(rct[i] @ w1 + b1) @ w2)[h]   grid 225, block 128
// ---------------------------------------------------------------------------
__device__ __forceinline__ float relcoord(int c) {
    float t = (float)c * (8.0f / 7.0f);
    float v = log2f(fabsf(t) + 1.0f) * (1.0f / 3.0f);   // /log2(8)
    return (t < 0.f) ? -v : (t > 0.f ? v : 0.f);
}

__global__ void k_table(const float* __restrict__ w1, const float* __restrict__ b1,
                        const float* __restrict__ w2) {
    const int i = blockIdx.x;
    const float r0 = relcoord(i / 15 - 7);
    const float r1 = relcoord(i % 15 - 7);
    float acc[8] = {0.f, 0.f, 0.f, 0.f, 0.f, 0.f, 0.f, 0.f};
    for (int j = threadIdx.x; j < 512; j += 128) {
        float h = fmaf(r0, w1[j], fmaf(r1, w1[512 + j], b1[j]));
        h = fmaxf(h, 0.f);
        #pragma unroll
        for (int q = 0; q < 8; q++) acc[q] = fmaf(h, w2[j * 8 + q], acc[q]);
    }
    __shared__ float red[4][8];
    #pragma unroll
    for (int q = 0; q < 8; q++) {
        float v = acc[q];
        v += __shfl_xor_sync(0xffffffffu, v, 16);
        v += __shfl_xor_sync(0xffffffffu, v, 8);
        v += __shfl_xor_sync(0xffffffffu, v, 4);
        v += __shfl_xor_sync(0xffffffffu, v, 2);
        v += __shfl_xor_sync(0xffffffffu, v, 1);
        if ((threadIdx.x & 31) == 0) red[threadIdx.x >> 5][q] = v;
    }
    __syncthreads();
    if (threadIdx.x < 8) {
        g_table[i * 8 + threadIdx.x] =
            red[0][threadIdx.x] + red[1][threadIdx.x] +
            red[2][threadIdx.x] + red[3][threadIdx.x];
    }
}

// ---------------------------------------------------------------------------
// bias16[h][n][m] = 16*sigmoid(table[rpi(n,m)][h]);  g_scale[h]
// ---------------------------------------------------------------------------
__global__ void k_bias(const float* __restrict__ ls) {
    const int n = blockIdx.x;
    const int t = threadIdx.x;
    const int h = t >> 6, m = t & 63;
    const int r1 = n >> 3, c1 = n & 7, r2 = m >> 3, c2 = m & 7;
    const int idx = (r1 - r2 + 7) * 15 + (c1 - c2 + 7);
    const float v = g_table[idx * 8 + h];
    g_bias16[(h << 12) + (n << 6) + m] = 16.f / (1.f + __expf(-v));
    if (n == 0 && t < 8)
        g_scale[t] = expf(fminf(ls[t], 4.6051701859880914f));   // ln(100)
}

// ---------------------------------------------------------------------------
// C[M x 65536] = W[M x 192] @ B[192 x 65536]  (TF32 mma)
// One CTA = 128-pixel strip, ALL M rows (B strip resident in smem -> the
// activation matrix is read exactly once from DRAM).
// MODE 0: QKV, bias=[q_bias,0,v_bias] -> g_qkv.  MODE 1: proj + b + residual.
// ---------------------------------------------------------------------------
template <int MODE>
__global__ void __launch_bounds__(256, 2) k_gemm(const float* __restrict__ Bg,
                                                 const float* __restrict__ W,
                                                 const float* __restrict__ bias0,
                                                 const float* __restrict__ bias1,
                                                 const float* __restrict__ resid,
                                                 float* __restrict__ outp) {
    extern __shared__ float smem[];
    float* sB = smem;                    // [192][BSTR]
    float* sA = smem + 192 * BSTR;       // [2][64][20]

    const int tid = threadIdx.x;
    const int bn = blockIdx.x * 128;
    const int b  = blockIdx.z;
    const float* src = (MODE == 0 ? Bg : g_att) + (size_t)b * CH * PIX;
    float* dst = (MODE == 0 ? g_qkv + (size_t)b * OC3 * PIX
                            : outp + (size_t)b * CH * PIX);

    const int warp = tid >> 5, lane = tid & 31, g = lane >> 2, tg = lane & 3;
    const int wm = warp >> 2, wn = warp & 3;
    constexpr int NBM = (MODE == 0) ? 9 : 3;

    // stage full B strip [192][128]
    for (int i = tid; i < 6144; i += 256) {
        const int row = i >> 5, c4 = (i & 31) * 4;
        cp16(&sB[row * BSTR + c4], &src[(size_t)row * PIX + bn + c4]);
    }
    asm volatile("cp.async.commit_group;");

    auto stageA = [&](int buf, int bm, int k0) {
        const int row = tid >> 2, cc = tid & 3;
        cp16(&sA[buf * 1280 + row * 20 + cc * 4],
             &W[(bm + row) * CH + k0 + cc * 4]);
        asm volatile("cp.async.commit_group;");
    };

    stageA(0, 0, 0);

    #pragma unroll 1
    for (int bmt = 0; bmt < NBM; bmt++) {
        const int bm = bmt * 64;
        float acc[2][4][4];
        #pragma unroll
        for (int i = 0; i < 2; i++)
            #pragma unroll
            for (int j = 0; j < 4; j++)
                #pragma unroll
                for (int k = 0; k < 4; k++) acc[i][j][k] = 0.f;

        #pragma unroll 1
        for (int kk = 0; kk < 12; kk++) {
            const int buf = kk & 1;
            bool staged = true;
            if (kk < 11)                stageA(buf ^ 1, bm, (kk + 1) * 16);
            else if (bmt + 1 < NBM)     stageA(buf ^ 1, bm + 64, 0);
            else                        staged = false;
            if (staged) asm volatile("cp.async.wait_group 1;");
            else        asm volatile("cp.async.wait_group 0;");
            __syncthreads();
            const float* A0 = sA + buf * 1280;
            #pragma unroll
            for (int ks = 0; ks < 2; ks++) {
                const int kb = kk * 16 + ks * 8;   // global k for B
                const int k  = ks * 8;             // local k for A chunk
                uint32_t bf[4][2];
                #pragma unroll
                for (int nt = 0; nt < 4; nt++) {
                    bf[nt][0] = f2tf(sB[(kb + tg) * BSTR + wn * 32 + nt * 8 + g]);
                    bf[nt][1] = f2tf(sB[(kb + tg + 4) * BSTR + wn * 32 + nt * 8 + g]);
                }
                #pragma unroll
                for (int mt = 0; mt < 2; mt++) {
                    const int r0 = wm * 32 + mt * 16;
                    uint32_t af[4];
                    af[0] = f2tf(A0[(r0 + g) * 20 + k + tg]);
                    af[1] = f2tf(A0[(r0 + g + 8) * 20 + k + tg]);
                    af[2] = f2tf(A0[(r0 + g) * 20 + k + tg + 4]);
                    af[3] = f2tf(A0[(r0 + g + 8) * 20 + k + tg + 4]);
                    #pragma unroll
                    for (int nt = 0; nt < 4; nt++) mma8(acc[mt][nt], af, bf[nt]);
                }
            }
            __syncthreads();
        }

        // register epilogue: bias (+residual) and float2 stores
        #pragma unroll
        for (int mt = 0; mt < 2; mt++) {
            const int r0 = wm * 32 + mt * 16;
            const int o_lo = bm + r0 + g, o_hi = o_lo + 8;
            float blo, bhi;
            if (MODE == 0) {
                blo = (o_lo < 192) ? bias0[o_lo] : (o_lo < 384 ? 0.f : bias1[o_lo - 384]);
                bhi = (o_hi < 192) ? bias0[o_hi] : (o_hi < 384 ? 0.f : bias1[o_hi - 384]);
            } else {
                blo = bias0[o_lo];
                bhi = bias0[o_hi];
            }
            #pragma unroll
            for (int nt = 0; nt < 4; nt++) {
                const int col = bn + wn * 32 + nt * 8 + 2 * tg;
                float2 v0 = make_float2(acc[mt][nt][0] + blo, acc[mt][nt][1] + blo);
                float2 v1 = make_float2(acc[mt][nt][2] + bhi, acc[mt][nt][3] + bhi);
                const size_t lo = (size_t)o_lo * PIX + col;
                const size_t hi = (size_t)o_hi * PIX + col;
                if (MODE == 1) {
                    const float* rbase = resid + (size_t)b * CH * PIX;
                    const float2 r0v = *(const float2*)&rbase[lo];
                    const float2 r1v = *(const float2*)&rbase[hi];
                    v0.x += r0v.x; v0.y += r0v.y;
                    v1.x += r1v.x; v1.y += r1v.y;
                }
                *(float2*)&dst[lo] = v0;
                *(float2*)&dst[hi] = v1;
            }
        }
    }
}

// ---------------------------------------------------------------------------
// Per-window attention. grid 4096; 512 threads = 16 warps; warp (h,half):
// head h = warp>>1, half = warp&1 owns mt tiles {2*half, 2*half+1}.
// Inverse norms + logit scale folded into mma fragment loads (no scale pass).
// ---------------------------------------------------------------------------
__global__ void __launch_bounds__(512, 1) k_attn() {
    extern __shared__ float sT[];                  // [576][TSTR]
    float* sInvQ = sT + 576 * TSTR;                // [8][64]
    float* sInvK = sInvQ + 512;                    // [8][64]

    const int tid = threadIdx.x, lane = tid & 31, warp = tid >> 5;
    const int g = lane >> 2, tg = lane & 3;
    const int h = warp >> 1, half = warp & 1;
    const int bx = blockIdx.x;
    const int wx = bx & 31, hy = (bx >> 5) & 31, b = bx >> 10;
    const int p0 = (hy << 11) + (wx << 3);
    const float* src = g_qkv + (size_t)b * OC3 * PIX + p0;

    // vectorized window gather: 9216 float4 loads (each window row = 2 float4)
    for (int i = tid; i < 576 * 16; i += 512) {
        const int o = i >> 4, j = i & 15;
        const int r = j >> 1, ch = (j & 1) * 4;
        const float4 v = *(const float4*)&src[(size_t)o * PIX + (r << 8) + ch];
        *(float4*)&sT[o * TSTR + r * 8 + ch] = v;
    }
    __syncthreads();

    // norms: one token per thread (8 heads x 64 tokens = 512 threads)
    {
        const int t = half * 32 + lane;
        const float* qp = sT + (h * 24) * TSTR + t;
        const float* kp = sT + (192 + h * 24) * TSTR + t;
        float sq = 0.f, sk = 0.f;
        #pragma unroll
        for (int d = 0; d < 24; d++) {
            const float q = qp[d * TSTR], k = kp[d * TSTR];
            sq = fmaf(q, q, sq);
            sk = fmaf(k, k, sk);
        }
        sInvQ[h * 64 + t] = g_scale[h] / fmaxf(sqrtf(sq), 1e-12f);
        sInvK[h * 64 + t] = 1.0f / fmaxf(sqrtf(sk), 1e-12f);
    }
    __syncthreads();

    const float* Q = sT + (h * 24) * TSTR;
    const float* K = sT + (192 + h * 24) * TSTR;
    const float* V = sT + (384 + h * 24) * TSTR;
    const float* bias = g_bias16 + (h << 12);
    float* dst = g_att + (size_t)b * CH * PIX + (size_t)(h * 24) * PIX + p0;

    float km[8];
    #pragma unroll
    for (int nt = 0; nt < 8; nt++) km[nt] = sInvK[h * 64 + nt * 8 + g];

    const int srcLo = (lane & 28) | (tg >> 1);
    const int srcHi = srcLo + 2;
    const bool odd = (tg & 1);

    #pragma unroll 1
    for (int mi = 0; mi < 2; mi++) {
        const int mt = half * 2 + mi;
        const int m0 = mt * 16;
        const float qm1 = sInvQ[h * 64 + m0 + g];
        const float qm2 = sInvQ[h * 64 + m0 + g + 8];

        // ---- S = (q/|q|*scale)^T (k/|k|)   [16 x 64] ----
        float s[8][4];
        #pragma unroll
        for (int nt = 0; nt < 8; nt++)
            #pragma unroll
            for (int e = 0; e < 4; e++) s[nt][e] = 0.f;

        #pragma unroll
        for (int kt = 0; kt < 3; kt++) {
            const int k0 = kt * 8;
            uint32_t a[4];
            a[0] = f2tf(Q[(k0 + tg) * TSTR + m0 + g] * qm1);
            a[1] = f2tf(Q[(k0 + tg) * TSTR + m0 + g + 8] * qm2);
            a[2] = f2tf(Q[(k0 + tg + 4) * TSTR + m0 + g] * qm1);
            a[3] = f2tf(Q[(k0 + tg + 4) * TSTR + m0 + g + 8] * qm2);
            #pragma unroll
            for (int nt = 0; nt < 8; nt++) {
                uint32_t bb[2];
                bb[0] = f2tf(K[(k0 + tg) * TSTR + nt * 8 + g] * km[nt]);
                bb[1] = f2tf(K[(k0 + tg + 4) * TSTR + nt * 8 + g] * km[nt]);
                mma8(s[nt], a, bb);
            }
        }

        // ---- + bias, softmax (rows r1 = m0+g, r2 = r1+8) ----
        const int r1 = m0 + g, r2 = r1 + 8;
        float mx1 = -1e30f, mx2 = -1e30f;
        #pragma unroll
        for (int nt = 0; nt < 8; nt++) {
            const int c0 = nt * 8 + 2 * tg;
            const float2 b1v = *(const float2*)&bias[(r1 << 6) + c0];
            const float2 b2v = *(const float2*)&bias[(r2 << 6) + c0];
            s[nt][0] += b1v.x; s[nt][1] += b1v.y;
            s[nt][2] += b2v.x; s[nt][3] += b2v.y;
            mx1 = fmaxf(mx1, fmaxf(s[nt][0], s[nt][1]));
            mx2 = fmaxf(mx2, fmaxf(s[nt][2], s[nt][3]));
        }
        mx1 = fmaxf(mx1, __shfl_xor_sync(0xffffffffu, mx1, 1));
        mx1 = fmaxf(mx1, __shfl_xor_sync(0xffffffffu, mx1, 2));
        mx2 = fmaxf(mx2, __shfl_xor_sync(0xffffffffu, mx2, 1));
        mx2 = fmaxf(mx2, __shfl_xor_sync(0xffffffffu, mx2, 2));
        float sum1 = 0.f, sum2 = 0.f;
        #pragma unroll
        for (int nt = 0; nt < 8; nt++) {
            s[nt][0] = __expf(s[nt][0] - mx1);
            s[nt][1] = __expf(s[nt][1] - mx1);
            s[nt][2] = __expf(s[nt][2] - mx2);
            s[nt][3] = __expf(s[nt][3] - mx2);
            sum1 += s[nt][0] + s[nt][1];
            sum2 += s[nt][2] + s[nt][3];
        }
        sum1 += __shfl_xor_sync(0xffffffffu, sum1, 1);
        sum1 += __shfl_xor_sync(0xffffffffu, sum1, 2);
        sum2 += __shfl_xor_sync(0xffffffffu, sum2, 1);
        sum2 += __shfl_xor_sync(0xffffffffu, sum2, 2);
        const float inv1 = 1.f / sum1, inv2 = 1.f / sum2;

        // ---- O = P @ V : P C-frag -> A-frag in registers via shfl ----
        float o_[3][4];
        #pragma unroll
        for (int nt = 0; nt < 3; nt++)
            #pragma unroll
            for (int e = 0; e < 4; e++) o_[nt][e] = 0.f;

        #pragma unroll
        for (int kt = 0; kt < 8; kt++) {
            const float v00 = __shfl_sync(0xffffffffu, s[kt][0], srcLo);
            const float v01 = __shfl_sync(0xffffffffu, s[kt][1], srcLo);
            const float v10 = __shfl_sync(0xffffffffu, s[kt][2], srcLo);
            const float v11 = __shfl_sync(0xffffffffu, s[kt][3], srcLo);
            const float w00 = __shfl_sync(0xffffffffu, s[kt][0], srcHi);
            const float w01 = __shfl_sync(0xffffffffu, s[kt][1], srcHi);
            const float w10 = __shfl_sync(0xffffffffu, s[kt][2], srcHi);
            const float w11 = __shfl_sync(0xffffffffu, s[kt][3], srcHi);
            uint32_t a[4];
            a[0] = f2tf(odd ? v01 : v00);   // P[m0+g  ][8kt+tg  ]
            a[1] = f2tf(odd ? v11 : v10);   // P[m0+g+8][8kt+tg  ]
            a[2] = f2tf(odd ? w01 : w00);   // P[m0+g  ][8kt+tg+4]
            a[3] = f2tf(odd ? w11 : w10);   // P[m0+g+8][8kt+tg+4]
            #pragma unroll
            for (int nt = 0; nt < 3; nt++) {
                uint32_t bb[2];
                bb[0] = f2tf(V[(nt * 8 + g) * TSTR + kt * 8 + tg]);
                bb[1] = f2tf(V[(nt * 8 + g) * TSTR + kt * 8 + tg + 4]);
                mma8(o_[nt], a, bb);
            }
        }

        // ---- store (fold 1/rowsum); window row = contiguous 32B sector ----
        const int p1 = ((r1 & 56) << 5) + (r1 & 7);
        const int p2 = ((r2 & 56) << 5) + (r2 & 7);
        #pragma unroll
        for (int nt = 0; nt < 3; nt++) {
            const int d0 = nt * 8 + 2 * tg;
            const size_t c1 = (size_t)d0 * PIX, c2 = c1 + PIX;
            dst[c1 + p1] = o_[nt][0] * inv1;
            dst[c2 + p1] = o_[nt][1] * inv1;
            dst[c1 + p2] = o_[nt][2] * inv2;
            dst[c2 + p2] = o_[nt][3] * inv2;
        }
    }
}

// ---------------------------------------------------------------------------
extern "C" void kernel_launch(void* const* d_in, const int* in_sizes, int n_in,
                              void* d_out, int out_size) {
    const float* x      = (const float*)d_in[0];
    // d_in[1] img_alpha unused (all-ones, no-op per reference)
    const float* qkv_w  = (const float*)d_in[2];
    const float* q_bias = (const float*)d_in[3];
    const float* v_bias = (const float*)d_in[4];
    const float* ls     = (const float*)d_in[5];
    const float* w1     = (const float*)d_in[6];
    const float* b1     = (const float*)d_in[7];
    const float* w2     = (const float*)d_in[8];
    const float* proj_w = (const float*)d_in[9];
    const float* proj_b = (const float*)d_in[10];
    float* out = (float*)d_out;

    const int attn_smem = ATTN_SMEM_FLOATS * 4;    // 160768 B
    const int gemm_smem = GEMM_SMEM_FLOATS * 4;    // 111616 B
    cudaFuncSetAttribute(k_attn, cudaFuncAttributeMaxDynamicSharedMemorySize,
                         attn_smem);
    cudaFuncSetAttribute(k_gemm<0>, cudaFuncAttributeMaxDynamicSharedMemorySize,
                         gemm_smem);
    cudaFuncSetAttribute(k_gemm<1>, cudaFuncAttributeMaxDynamicSharedMemorySize,
                         gemm_smem);

    k_table<<<225, 128>>>(w1, b1, w2);
    k_bias<<<64, 512>>>(ls);
    dim3 g0(512, 1, BATCH);
    k_gemm<0><<<g0, 256, gemm_smem>>>(x, qkv_w, q_bias, v_bias, nullptr, nullptr);
    k_attn<<<4096, 512, attn_smem>>>();
    dim3 g1(512, 1, BATCH);
    k_gemm<1><<<g1, 256, gemm_smem>>>(nullptr, proj_w, proj_b, nullptr, x, out);
}